// round 2
// baseline (speedup 1.0000x reference)
#include <cuda_runtime.h>

// FuzzyARTMAP match scores + argmax for N=1024, D=256, C=512 (fp32).
// match[n,c] = sum_d min(x[n,d], w[c,d]) / sum_d x[n,d]; gate at 0.75; argmax per row.

#define N_ROWS 1024
#define D_DIM  256
#define C_CATS 512
#define VIG    0.75f

#define BM 64
#define BN 64
#define BK 64
#define LSTRIDE 65   // pad to break bank conflicts on strided column access

__device__ float g_xsum[N_ROWS];

// ---------------------------------------------------------------------------
// Kernel 0: per-row sum of x. One warp per row, 8 rows per block.
// ---------------------------------------------------------------------------
__global__ __launch_bounds__(256) void xsum_kernel(const float* __restrict__ x) {
    int warp = threadIdx.x >> 5;
    int lane = threadIdx.x & 31;
    int row  = blockIdx.x * 8 + warp;
    if (row >= N_ROWS) return;
    const float4* xr = (const float4*)(x + (size_t)row * D_DIM);
    float s = 0.f;
    #pragma unroll
    for (int i = 0; i < D_DIM / 4 / 32; i++) {   // 256/4 = 64 float4, 32 lanes -> 2 each
        float4 v = xr[lane + 32 * i];
        s += v.x + v.y + v.z + v.w;
    }
    #pragma unroll
    for (int o = 16; o > 0; o >>= 1) s += __shfl_xor_sync(0xffffffffu, s, o);
    if (lane == 0) g_xsum[row] = s;
}

// ---------------------------------------------------------------------------
// Kernel 1: tiled min-plus "GEMM" + vigilance gate.
// Grid (C/BN, N/BM) = (8,16) = 128 blocks, 256 threads, 4x4 register tile.
// Thread (tx,ty), tx=t&15, ty=t>>4. Rows = base + 4*ty + i, cols = base + tx + 16*j.
// ---------------------------------------------------------------------------
__global__ __launch_bounds__(256) void scores_kernel(const float* __restrict__ x,
                                                     const float* __restrict__ w,
                                                     float* __restrict__ out) {
    __shared__ float As[BM][LSTRIDE];  // x tile, [m][k]
    __shared__ float Bs[BN][LSTRIDE];  // w tile, [c][k]

    const int t  = threadIdx.x;
    const int tx = t & 15;
    const int ty = t >> 4;
    const int rowBase = blockIdx.y * BM;
    const int colBase = blockIdx.x * BN;

    // tile-load mapping: 4 float4 per array per thread
    const int lr = t >> 4;   // 0..15
    const int lc = t & 15;   // float4 column index, 0..15 (BK/4 = 16)

    float acc[4][4];
    #pragma unroll
    for (int i = 0; i < 4; i++)
        #pragma unroll
        for (int j = 0; j < 4; j++) acc[i][j] = 0.f;

    for (int k0 = 0; k0 < D_DIM; k0 += BK) {
        #pragma unroll
        for (int i = 0; i < 4; i++) {
            int r = lr + 16 * i;
            float4 v = *(const float4*)(x + (size_t)(rowBase + r) * D_DIM + k0 + 4 * lc);
            As[r][4 * lc + 0] = v.x;
            As[r][4 * lc + 1] = v.y;
            As[r][4 * lc + 2] = v.z;
            As[r][4 * lc + 3] = v.w;
        }
        #pragma unroll
        for (int i = 0; i < 4; i++) {
            int r = lr + 16 * i;
            float4 v = *(const float4*)(w + (size_t)(colBase + r) * D_DIM + k0 + 4 * lc);
            Bs[r][4 * lc + 0] = v.x;
            Bs[r][4 * lc + 1] = v.y;
            Bs[r][4 * lc + 2] = v.z;
            Bs[r][4 * lc + 3] = v.w;
        }
        __syncthreads();

        #pragma unroll 16
        for (int k = 0; k < BK; k++) {
            float a0 = As[4 * ty + 0][k];
            float a1 = As[4 * ty + 1][k];
            float a2 = As[4 * ty + 2][k];
            float a3 = As[4 * ty + 3][k];
            float b0 = Bs[tx +  0][k];
            float b1 = Bs[tx + 16][k];
            float b2 = Bs[tx + 32][k];
            float b3 = Bs[tx + 48][k];

            acc[0][0] += fminf(a0, b0); acc[0][1] += fminf(a0, b1);
            acc[0][2] += fminf(a0, b2); acc[0][3] += fminf(a0, b3);
            acc[1][0] += fminf(a1, b0); acc[1][1] += fminf(a1, b1);
            acc[1][2] += fminf(a1, b2); acc[1][3] += fminf(a1, b3);
            acc[2][0] += fminf(a2, b0); acc[2][1] += fminf(a2, b1);
            acc[2][2] += fminf(a2, b2); acc[2][3] += fminf(a2, b3);
            acc[3][0] += fminf(a3, b0); acc[3][1] += fminf(a3, b1);
            acc[3][2] += fminf(a3, b2); acc[3][3] += fminf(a3, b3);
        }
        __syncthreads();
    }

    #pragma unroll
    for (int i = 0; i < 4; i++) {
        int n = rowBase + 4 * ty + i;
        float xs = g_xsum[n];
        #pragma unroll
        for (int j = 0; j < 4; j++) {
            int c = colBase + tx + 16 * j;
            float m = acc[i][j] / xs;          // match division exactly as reference
            out[(size_t)n * C_CATS + c] = (m >= VIG) ? m : 0.f;
        }
    }
}

// ---------------------------------------------------------------------------
// Kernel 2: per-row argmax with first-occurrence tie-break (jnp.argmax semantics).
// One block per row, 128 threads, 4 values each.
// ---------------------------------------------------------------------------
__global__ __launch_bounds__(128) void argmax_kernel(const float* __restrict__ scores,
                                                     float* __restrict__ idx_out) {
    __shared__ float sv[128];
    __shared__ int   si[128];
    const int n = blockIdx.x;
    const int t = threadIdx.x;
    const float* row = scores + (size_t)n * C_CATS;

    float bv = -1.f;
    int   bi = 0;
    #pragma unroll
    for (int j = 0; j < C_CATS / 128; j++) {
        int c = t + 128 * j;
        float v = row[c];
        if (v > bv || (v == bv && c < bi)) { bv = v; bi = c; }
    }
    sv[t] = bv;
    si[t] = bi;
    __syncthreads();
    #pragma unroll
    for (int s = 64; s > 0; s >>= 1) {
        if (t < s) {
            float ov = sv[t + s];
            int   oi = si[t + s];
            if (ov > sv[t] || (ov == sv[t] && oi < si[t])) { sv[t] = ov; si[t] = oi; }
        }
        __syncthreads();
    }
    if (t == 0) idx_out[n] = (float)si[0];
}

// ---------------------------------------------------------------------------
extern "C" void kernel_launch(void* const* d_in, const int* in_sizes, int n_in,
                              void* d_out, int out_size) {
    const float* x = (const float*)d_in[0];
    const float* w = (const float*)d_in[1];
    float* out = (float*)d_out;

    // Kernel 0: row sums (1024 rows, 8 per block)
    xsum_kernel<<<N_ROWS / 8, 256>>>(x);

    // Kernel 1: match scores
    dim3 grid(C_CATS / BN, N_ROWS / BM);   // (8, 16)
    scores_kernel<<<grid, 256>>>(x, w, out);

    // Kernel 2: argmax indices appended after the score matrix (if expected)
    if (out_size >= N_ROWS * C_CATS + N_ROWS) {
        argmax_kernel<<<N_ROWS, 128>>>(out, out + (size_t)N_ROWS * C_CATS);
    }
}

// round 3
// speedup vs baseline: 1.2076x; 1.2076x over previous
#include <cuda_runtime.h>

// FuzzyARTMAP fused: match scores + row sums + argmax for N=1024, D=256, C=512 (fp32).
// match[n,c] = sum_d min(x[n,d], w[c,d]) / sum_d x[n,d]; gate at 0.75; first-occurrence argmax.
//
// Kernel A (scores_kernel): tiled min-plus GEMM, 128 blocks, fused row-sum over the
//   As tiles it already loads, fused per-block argmax reduced via smem+global atomicMax
//   on an order-preserving 64-bit key.
// Kernel B (decode_kernel): 1024 keys -> float indices, and resets the key array so the
//   launch sequence is idempotent under CUDA-graph replay.

#define N_ROWS 1024
#define D_DIM  256
#define C_CATS 512
#define VIG    0.75f

#define BM 64
#define BN 64
#define BK 64
#define LSTRIDE 68   // 68 words = 272B row stride: 16B-aligned for LDS.128, conflict-free

__device__ unsigned long long g_key[N_ROWS];   // zero-initialized at module load; decode resets

// ---------------------------------------------------------------------------
__global__ __launch_bounds__(256) void scores_kernel(const float* __restrict__ x,
                                                     const float* __restrict__ w,
                                                     float* __restrict__ out) {
    __shared__ float As[BM][LSTRIDE];                 // x tile, [m][k]
    __shared__ float Bs[BN][LSTRIDE];                 // w tile, [c][k]
    __shared__ float xq[BM][4];                       // per-row quarter sums of x
    __shared__ unsigned long long skey[BM];           // per-row best (val,col) key

    const int t  = threadIdx.x;
    const int tx = t & 15;
    const int ty = t >> 4;
    const int rowBase = blockIdx.y * BM;
    const int colBase = blockIdx.x * BN;

    // tile-load mapping: 4 float4 per array per thread
    const int lr = t >> 4;   // 0..15
    const int lc = t & 15;   // float4 column index (BK/4 = 16)

    float acc[4][4];
    #pragma unroll
    for (int i = 0; i < 4; i++)
        #pragma unroll
        for (int j = 0; j < 4; j++) acc[i][j] = 0.f;

    float xpart = 0.f;                 // this thread's share of row sums
    const int xr = t >> 2;             // row for xsum duty (0..63)
    const int xc = (t & 3) * 16;       // quarter offset within the BK tile

    if (t < BM) skey[t] = 0ull;

    for (int k0 = 0; k0 < D_DIM; k0 += BK) {
        #pragma unroll
        for (int i = 0; i < 4; i++) {
            int r = lr + 16 * i;
            float4 v = *(const float4*)(x + (size_t)(rowBase + r) * D_DIM + k0 + 4 * lc);
            *(float4*)&As[r][4 * lc] = v;
        }
        #pragma unroll
        for (int i = 0; i < 4; i++) {
            int r = lr + 16 * i;
            float4 v = *(const float4*)(w + (size_t)(colBase + r) * D_DIM + k0 + 4 * lc);
            *(float4*)&Bs[r][4 * lc] = v;
        }
        __syncthreads();

        // fused xsum: each thread sums a 16-wide quarter of one As row
        {
            const float* rp = &As[xr][xc];
            float s = 0.f;
            #pragma unroll
            for (int u = 0; u < 4; u++) {
                float4 v = *(const float4*)(rp + 4 * u);
                s += v.x + v.y + v.z + v.w;
            }
            xpart += s;
        }

        #pragma unroll 4
        for (int k = 0; k < BK; k += 4) {
            float4 a0 = *(const float4*)&As[4 * ty + 0][k];
            float4 a1 = *(const float4*)&As[4 * ty + 1][k];
            float4 a2 = *(const float4*)&As[4 * ty + 2][k];
            float4 a3 = *(const float4*)&As[4 * ty + 3][k];
            float4 b0 = *(const float4*)&Bs[tx +  0][k];
            float4 b1 = *(const float4*)&Bs[tx + 16][k];
            float4 b2 = *(const float4*)&Bs[tx + 32][k];
            float4 b3 = *(const float4*)&Bs[tx + 48][k];

            #define STEP(F)                                        \
                acc[0][0] += fminf(a0.F, b0.F);                    \
                acc[0][1] += fminf(a0.F, b1.F);                    \
                acc[0][2] += fminf(a0.F, b2.F);                    \
                acc[0][3] += fminf(a0.F, b3.F);                    \
                acc[1][0] += fminf(a1.F, b0.F);                    \
                acc[1][1] += fminf(a1.F, b1.F);                    \
                acc[1][2] += fminf(a1.F, b2.F);                    \
                acc[1][3] += fminf(a1.F, b3.F);                    \
                acc[2][0] += fminf(a2.F, b0.F);                    \
                acc[2][1] += fminf(a2.F, b1.F);                    \
                acc[2][2] += fminf(a2.F, b2.F);                    \
                acc[2][3] += fminf(a2.F, b3.F);                    \
                acc[3][0] += fminf(a3.F, b0.F);                    \
                acc[3][1] += fminf(a3.F, b1.F);                    \
                acc[3][2] += fminf(a3.F, b2.F);                    \
                acc[3][3] += fminf(a3.F, b3.F);
            STEP(x) STEP(y) STEP(z) STEP(w)
            #undef STEP
        }
        __syncthreads();
    }

    // publish quarter sums, combine per row
    xq[xr][t & 3] = xpart;
    __syncthreads();

    #pragma unroll
    for (int i = 0; i < 4; i++) {
        int r = 4 * ty + i;
        int n = rowBase + r;
        float xs = xq[r][0] + xq[r][1] + xq[r][2] + xq[r][3];
        unsigned long long bk = 0ull;
        #pragma unroll
        for (int j = 0; j < 4; j++) {
            int c = colBase + tx + 16 * j;
            float m = acc[i][j] / xs;                       // exact division, as reference
            float g = (m >= VIG) ? m : 0.f;
            out[(size_t)n * C_CATS + c] = g;
            // order-preserving key: larger value wins; ties -> larger (C-1-c) -> smaller c
            unsigned long long key =
                ((unsigned long long)__float_as_uint(g) << 32) |
                (unsigned long long)(unsigned)(C_CATS - 1 - c);
            if (key > bk) bk = key;
        }
        atomicMax(&skey[r], bk);
    }
    __syncthreads();

    if (t < BM) atomicMax(&g_key[rowBase + t], skey[t]);
}

// ---------------------------------------------------------------------------
// Decode keys -> float indices, then reset keys so the next graph replay starts clean.
__global__ __launch_bounds__(256) void decode_kernel(float* __restrict__ idx_out) {
    int n = blockIdx.x * 256 + threadIdx.x;
    unsigned long long k = g_key[n];
    if (idx_out) idx_out[n] = (float)(C_CATS - 1 - (unsigned)(k & 0xffffffffull));
    g_key[n] = 0ull;
}

// ---------------------------------------------------------------------------
extern "C" void kernel_launch(void* const* d_in, const int* in_sizes, int n_in,
                              void* d_out, int out_size) {
    const float* x = (const float*)d_in[0];
    const float* w = (const float*)d_in[1];
    float* out = (float*)d_out;

    dim3 grid(C_CATS / BN, N_ROWS / BM);   // (8, 16) = 128 blocks
    scores_kernel<<<grid, 256>>>(x, w, out);

    float* idx_out = (out_size >= N_ROWS * C_CATS + N_ROWS)
                   ? out + (size_t)N_ROWS * C_CATS : nullptr;
    decode_kernel<<<N_ROWS / 256, 256>>>(idx_out);
}